// round 1
// baseline (speedup 1.0000x reference)
#include <cuda_runtime.h>
#include <cuda_bf16.h>

// ---------------------------------------------------------------------------
// GatedSelfAttention  (B=16, LW=512, LE=128, L=640, D=1024, H=16, DH=64)
// fp32 throughout.  f32x2 packed FMA for all inner loops (B300: scalar FFMA
// is half-rate, fma.rn.f32x2 reaches fp32 peak).
// ---------------------------------------------------------------------------

#define BB   16
#define LW   512
#define LE   128
#define LL   640
#define DD   1024
#define HH   16
#define DHH  64

typedef unsigned long long ull;

__device__ __forceinline__ ull pk2(float x, float y) {
    ull r; asm("mov.b64 %0, {%1,%2};" : "=l"(r) : "f"(x), "f"(y)); return r;
}
__device__ __forceinline__ float2 up2(ull v) {
    float2 r; asm("mov.b64 {%0,%1}, %2;" : "=f"(r.x), "=f"(r.y) : "l"(v)); return r;
}
__device__ __forceinline__ void fma2(ull &c, ull a, ull b) {
    asm("fma.rn.f32x2 %0, %1, %2, %0;" : "+l"(c) : "l"(a), "l"(b));
}
__device__ __forceinline__ void mul2(ull &d, ull a, ull b) {
    asm("mul.rn.f32x2 %0, %1, %2;" : "=l"(d) : "l"(a), "l"(b));
}

// ---------------------------------------------------------------------------
// Scratch (device globals; allocation-free)
// ---------------------------------------------------------------------------
__device__ float g_Q  [BB * HH * LL * DHH];   // [B,H,L,64]
__device__ float g_K  [BB * HH * LL * DHH];
__device__ float g_V  [BB * HH * LL * DHH];
__device__ float g_GQW[BB * HH * LW * DHH];   // w2e_q  (word rows)
__device__ float g_GKW[BB * HH * LW * DHH];   // e2w_k  (word rows)
__device__ float g_GQE[BB * HH * LE * DHH];   // e2w_q  (entity rows)
__device__ float g_GKE[BB * HH * LE * DHH];   // w2e_k  (entity rows)

// ---------------------------------------------------------------------------
// Projection GEMM:  out[b,h,l,dh] = X[m,:] @ W[:,n] + bias[n]
// X rows come from word (l < LWx) or entity (l >= LWx).
// Tile: 128x128x8, 256 threads, 8x8 per thread, f32x2 accumulators.
// M = B*Lx must be a multiple of 128 (true for 640/512/128).
// ---------------------------------------------------------------------------
__global__ __launch_bounds__(256) void proj_kernel(
    const float* __restrict__ srcW, const float* __restrict__ srcE,
    int Lx, int LWx, int LEx,
    const float* __restrict__ W, const float* __restrict__ bias,
    float* __restrict__ out)
{
    __shared__ float As[8][132];   // A transposed: As[k][m]
    __shared__ float Bs[8][128];   // Bs[k][n]

    const int tid   = threadIdx.x;
    const int mBase = blockIdx.x * 128;
    const int nBase = blockIdx.y * 128;
    const int ty = tid >> 4, tx = tid & 15;

    // A loader: row am, 4 consecutive k
    const int am = tid >> 1;
    const int ak = (tid & 1) * 4;
    {
        // nothing
    }
    const int gm = mBase + am;
    const int ab = gm / Lx;
    const int al = gm % Lx;
    const float* arow = (al < LWx)
        ? srcW + ((size_t)ab * LWx + al) * DD + ak
        : srcE + ((size_t)ab * LEx + (al - LWx)) * DD + ak;

    // B loader: row bk, 4 consecutive n
    const int bk = tid >> 5;
    const int bn = (tid & 31) * 4;
    const float* brow = W + (size_t)bk * DD + nBase + bn;

    ull acc[8][4];
#pragma unroll
    for (int i = 0; i < 8; i++)
#pragma unroll
        for (int j = 0; j < 4; j++) acc[i][j] = 0ULL;

    for (int k0 = 0; k0 < DD; k0 += 8) {
        float4 av = *(const float4*)(arow); arow += 8;
        float4 bv = *(const float4*)(brow); brow += 8 * DD;
        As[ak + 0][am] = av.x;
        As[ak + 1][am] = av.y;
        As[ak + 2][am] = av.z;
        As[ak + 3][am] = av.w;
        *(float4*)&Bs[bk][bn] = bv;
        __syncthreads();
#pragma unroll
        for (int kk = 0; kk < 8; kk++) {
            float4 a0 = *(const float4*)&As[kk][ty * 8];
            float4 a1 = *(const float4*)&As[kk][ty * 8 + 4];
            ulonglong2 b0 = *(const ulonglong2*)&Bs[kk][tx * 8];
            ulonglong2 b1 = *(const ulonglong2*)&Bs[kk][tx * 8 + 4];
            float aa[8] = {a0.x, a0.y, a0.z, a0.w, a1.x, a1.y, a1.z, a1.w};
#pragma unroll
            for (int i = 0; i < 8; i++) {
                ull ad = pk2(aa[i], aa[i]);
                fma2(acc[i][0], ad, b0.x);
                fma2(acc[i][1], ad, b0.y);
                fma2(acc[i][2], ad, b1.x);
                fma2(acc[i][3], ad, b1.y);
            }
        }
        __syncthreads();
    }

    // epilogue: add bias, write head-major [B,H,Lx,64]
    const int n0 = nBase + tx * 8;
    const int h  = n0 >> 6;          // 8 consecutive n never straddle a head
    const int dh = n0 & 63;
    float4 bv0 = *(const float4*)(bias + n0);
    float4 bv1 = *(const float4*)(bias + n0 + 4);

#pragma unroll
    for (int i = 0; i < 8; i++) {
        int gm2 = mBase + ty * 8 + i;
        int b2  = gm2 / Lx;
        int l2  = gm2 % Lx;
        float* orow = out + (((size_t)b2 * HH + h) * Lx + l2) * DHH + dh;
        float2 u0 = up2(acc[i][0]);
        float2 u1 = up2(acc[i][1]);
        float2 u2 = up2(acc[i][2]);
        float2 u3 = up2(acc[i][3]);
        float4 r0 = {u0.x + bv0.x, u0.y + bv0.y, u1.x + bv0.z, u1.y + bv0.w};
        float4 r1 = {u2.x + bv1.x, u2.y + bv1.y, u3.x + bv1.z, u3.y + bv1.w};
        *(float4*)(orow)     = r0;
        *(float4*)(orow + 4) = r1;
    }
}

// ---------------------------------------------------------------------------
// Fused attention: per (b, h, 64-row q tile).
//   S = Q K^T ; gate = -5 (same side) or -10*sigmoid(Gq Gk^T) (cross)
//   S = (S + gate)/8 + mask ; online softmax ; O = P V ; O /= l
// smem strides: SQ=68 (vector tiles), SP=65 (P, scalar broadcast reads)
// ---------------------------------------------------------------------------
#define SQ 68
#define SP 65

__global__ __launch_bounds__(256, 2) void attn_kernel(
    const float* __restrict__ Q, const float* __restrict__ K, const float* __restrict__ V,
    const float* __restrict__ GQW, const float* __restrict__ GKW,
    const float* __restrict__ GQE, const float* __restrict__ GKE,
    const float* __restrict__ mask, float* __restrict__ out)
{
    extern __shared__ float sm[];
    float* Qt    = sm;                 // [64][SQ]  Qt[d][i]
    float* Gqt   = Qt  + 64 * SQ;      // [64][SQ]
    float* Kt    = Gqt + 64 * SQ;      // [64][SQ]  Kt[d][j]
    float* Gkt   = Kt  + 64 * SQ;      // [64][SQ]
    float* Vs    = Gkt + 64 * SQ;      // [64][SQ]  Vs[k][dh]
    float* Ps    = Vs  + 64 * SQ;      // [64][SP]  Ps[i][k]
    float* maskS = Ps  + 64 * SP;      // [64]

    const int tid = threadIdx.x;
    const int qt  = blockIdx.x;
    const int h   = blockIdx.y;
    const int b   = blockIdx.z;
    const int q0  = qt * 64;
    const bool qWord = (q0 < LW);
    const int ty = tid >> 4, tx = tid & 15;

    const size_t bh = (size_t)(b * HH + h);
    const float* Qsrc  = Q + (bh * LL + q0) * DHH;
    const float* gqsrc = qWord ? GQW + (bh * LW + q0) * DHH
                               : GQE + (bh * LE + (q0 - LW)) * DHH;

    // load Qt, Gqt transposed (conflict-free: warp covers 32 distinct cols)
    {
        const int j  = tid & 63;
        const int dg = (tid >> 6) * 16;
        const float* s = Qsrc  + j * DHH + dg;
        const float* g = gqsrc + j * DHH + dg;
#pragma unroll
        for (int c = 0; c < 16; c += 4) {
            float4 v = *(const float4*)(s + c);
            Qt[(dg + c + 0) * SQ + j] = v.x;
            Qt[(dg + c + 1) * SQ + j] = v.y;
            Qt[(dg + c + 2) * SQ + j] = v.z;
            Qt[(dg + c + 3) * SQ + j] = v.w;
            float4 w = *(const float4*)(g + c);
            Gqt[(dg + c + 0) * SQ + j] = w.x;
            Gqt[(dg + c + 1) * SQ + j] = w.y;
            Gqt[(dg + c + 2) * SQ + j] = w.z;
            Gqt[(dg + c + 3) * SQ + j] = w.w;
        }
    }

    ull o2[4][2];
    float m_run[4], l_run[4];
#pragma unroll
    for (int r = 0; r < 4; r++) {
        o2[r][0] = 0ULL; o2[r][1] = 0ULL;
        m_run[r] = -1e30f; l_run[r] = 0.0f;
    }

    for (int kt = 0; kt < 10; kt++) {
        const int  k0    = kt * 64;
        const bool kWord = (k0 < LW);
        const bool cross = (kWord != qWord);

        __syncthreads();   // prev PV done before overwriting Kt/Vs

        // load Kt (+Gkt) transposed
        {
            const int j  = tid & 63;
            const int dg = (tid >> 6) * 16;
            const float* s = K + (bh * LL + k0 + j) * DHH + dg;
#pragma unroll
            for (int c = 0; c < 16; c += 4) {
                float4 v = *(const float4*)(s + c);
                Kt[(dg + c + 0) * SQ + j] = v.x;
                Kt[(dg + c + 1) * SQ + j] = v.y;
                Kt[(dg + c + 2) * SQ + j] = v.z;
                Kt[(dg + c + 3) * SQ + j] = v.w;
            }
            if (cross) {
                const float* g = qWord
                    ? GKE + (bh * LE + (k0 - LW) + j) * DHH + dg
                    : GKW + (bh * LW +  k0       + j) * DHH + dg;
#pragma unroll
                for (int c = 0; c < 16; c += 4) {
                    float4 w = *(const float4*)(g + c);
                    Gkt[(dg + c + 0) * SQ + j] = w.x;
                    Gkt[(dg + c + 1) * SQ + j] = w.y;
                    Gkt[(dg + c + 2) * SQ + j] = w.z;
                    Gkt[(dg + c + 3) * SQ + j] = w.w;
                }
            }
        }
        // load Vs (natural layout, coalesced)
#pragma unroll
        for (int it = 0; it < 4; it++) {
            int idx = tid + it * 256;
            int row = idx >> 4;
            int cg  = (idx & 15) * 4;
            float4 v = *(const float4*)(V + (bh * LL + k0 + row) * DHH + cg);
            *(float4*)&Vs[row * SQ + cg] = v;
        }
        if (tid < 16) {
            float4 mv = *(const float4*)(mask + (size_t)b * LL + k0 + tid * 4);
            *(float4*)&maskS[tid * 4] = mv;
        }
        __syncthreads();

        // ---- S (and gate) GEMM ----
        ull s2[4][2] = {{0ULL,0ULL},{0ULL,0ULL},{0ULL,0ULL},{0ULL,0ULL}};
        ull g2[4][2] = {{0ULL,0ULL},{0ULL,0ULL},{0ULL,0ULL},{0ULL,0ULL}};
        if (cross) {
#pragma unroll 2
            for (int d = 0; d < 64; d++) {
                float4 qv = *(const float4*)&Qt [d * SQ + ty * 4];
                float4 kv = *(const float4*)&Kt [d * SQ + tx * 4];
                float4 gq = *(const float4*)&Gqt[d * SQ + ty * 4];
                float4 gk = *(const float4*)&Gkt[d * SQ + tx * 4];
                ull k01 = pk2(kv.x, kv.y), k23 = pk2(kv.z, kv.w);
                ull e01 = pk2(gk.x, gk.y), e23 = pk2(gk.z, gk.w);
                float qa[4] = {qv.x, qv.y, qv.z, qv.w};
                float ga[4] = {gq.x, gq.y, gq.z, gq.w};
#pragma unroll
                for (int r = 0; r < 4; r++) {
                    ull qd = pk2(qa[r], qa[r]);
                    fma2(s2[r][0], qd, k01);
                    fma2(s2[r][1], qd, k23);
                    ull gd = pk2(ga[r], ga[r]);
                    fma2(g2[r][0], gd, e01);
                    fma2(g2[r][1], gd, e23);
                }
            }
        } else {
#pragma unroll 4
            for (int d = 0; d < 64; d++) {
                float4 qv = *(const float4*)&Qt[d * SQ + ty * 4];
                float4 kv = *(const float4*)&Kt[d * SQ + tx * 4];
                ull k01 = pk2(kv.x, kv.y), k23 = pk2(kv.z, kv.w);
                float qa[4] = {qv.x, qv.y, qv.z, qv.w};
#pragma unroll
                for (int r = 0; r < 4; r++) {
                    ull qd = pk2(qa[r], qa[r]);
                    fma2(s2[r][0], qd, k01);
                    fma2(s2[r][1], qd, k23);
                }
            }
        }

        // ---- gate + scale + mask + online softmax ----
        float p[4][4];
#pragma unroll
        for (int r = 0; r < 4; r++) {
            float2 u0 = up2(s2[r][0]);
            float2 u1 = up2(s2[r][1]);
            float sv[4] = {u0.x, u0.y, u1.x, u1.y};
            if (cross) {
                float2 w0 = up2(g2[r][0]);
                float2 w1 = up2(g2[r][1]);
                float gv[4] = {w0.x, w0.y, w1.x, w1.y};
#pragma unroll
                for (int c = 0; c < 4; c++)
                    sv[c] += -10.0f / (1.0f + __expf(-gv[c]));
            } else {
#pragma unroll
                for (int c = 0; c < 4; c++) sv[c] -= 5.0f;
            }
#pragma unroll
            for (int c = 0; c < 4; c++)
                sv[c] = sv[c] * 0.125f + maskS[tx * 4 + c];

            float mr = fmaxf(fmaxf(sv[0], sv[1]), fmaxf(sv[2], sv[3]));
#pragma unroll
            for (int off = 8; off >= 1; off >>= 1)
                mr = fmaxf(mr, __shfl_xor_sync(0xffffffffu, mr, off));
            float mnew = fmaxf(m_run[r], mr);
            float corr = __expf(m_run[r] - mnew);
            m_run[r] = mnew;
            float rs = 0.0f;
#pragma unroll
            for (int c = 0; c < 4; c++) {
                p[r][c] = __expf(sv[c] - mnew);
                rs += p[r][c];
            }
#pragma unroll
            for (int off = 8; off >= 1; off >>= 1)
                rs += __shfl_xor_sync(0xffffffffu, rs, off);
            l_run[r] = l_run[r] * corr + rs;
            ull cd = pk2(corr, corr);
            mul2(o2[r][0], o2[r][0], cd);
            mul2(o2[r][1], o2[r][1], cd);
        }

        // store P
#pragma unroll
        for (int r = 0; r < 4; r++)
#pragma unroll
            for (int c = 0; c < 4; c++)
                Ps[(ty * 4 + r) * SP + tx * 4 + c] = p[r][c];
        __syncthreads();

        // ---- PV GEMM ----
#pragma unroll 4
        for (int kk = 0; kk < 64; kk++) {
            float4 vv = *(const float4*)&Vs[kk * SQ + tx * 4];
            ull v01 = pk2(vv.x, vv.y), v23 = pk2(vv.z, vv.w);
#pragma unroll
            for (int r = 0; r < 4; r++) {
                float pr = Ps[(ty * 4 + r) * SP + kk];
                ull pd = pk2(pr, pr);
                fma2(o2[r][0], pd, v01);
                fma2(o2[r][1], pd, v23);
            }
        }
    }

    // ---- epilogue: O /= l, write split word/entity output ----
#pragma unroll
    for (int r = 0; r < 4; r++) {
        float inv = 1.0f / l_run[r];
        float2 a0 = up2(o2[r][0]);
        float2 a1 = up2(o2[r][1]);
        float4 o = {a0.x * inv, a0.y * inv, a1.x * inv, a1.y * inv};
        int q = q0 + ty * 4 + r;
        size_t off;
        if (q < LW)
            off = ((size_t)b * LW + q) * DD + h * DHH + tx * 4;
        else
            off = (size_t)BB * LW * DD +
                  ((size_t)b * LE + (q - LW)) * DD + h * DHH + tx * 4;
        *(float4*)(out + off) = o;
    }
}

// ---------------------------------------------------------------------------
// Launch
// ---------------------------------------------------------------------------
extern "C" void kernel_launch(void* const* d_in, const int* in_sizes, int n_in,
                              void* d_out, int out_size)
{
    const float* word   = (const float*)d_in[0];
    const float* entity = (const float*)d_in[1];
    const float* mask   = (const float*)d_in[2];
    // layer_num may or may not be materialized as an input; detect by size.
    int base = (in_sizes[3] == 1) ? 4 : 3;
    const float* qw     = (const float*)d_in[base + 0];
    const float* qb     = (const float*)d_in[base + 1];
    const float* kw     = (const float*)d_in[base + 2];
    const float* kb     = (const float*)d_in[base + 3];
    const float* vw     = (const float*)d_in[base + 4];
    const float* vb     = (const float*)d_in[base + 5];
    const float* w2e_qw = (const float*)d_in[base + 6];
    const float* w2e_qb = (const float*)d_in[base + 7];
    const float* w2e_kw = (const float*)d_in[base + 8];
    const float* w2e_kb = (const float*)d_in[base + 9];
    const float* e2w_qw = (const float*)d_in[base + 10];
    const float* e2w_qb = (const float*)d_in[base + 11];
    const float* e2w_kw = (const float*)d_in[base + 12];
    const float* e2w_kb = (const float*)d_in[base + 13];

    float *pQ, *pK, *pV, *pGQW, *pGKW, *pGQE, *pGKE;
    cudaGetSymbolAddress((void**)&pQ,   g_Q);
    cudaGetSymbolAddress((void**)&pK,   g_K);
    cudaGetSymbolAddress((void**)&pV,   g_V);
    cudaGetSymbolAddress((void**)&pGQW, g_GQW);
    cudaGetSymbolAddress((void**)&pGKW, g_GKW);
    cudaGetSymbolAddress((void**)&pGQE, g_GQE);
    cudaGetSymbolAddress((void**)&pGKE, g_GKE);

    dim3 blk(256);
    // q/k/v on concat(word, entity): M = 16*640 = 10240
    proj_kernel<<<dim3(80, 8), blk>>>(word, entity, LL, LW, LE, qw, qb, pQ);
    proj_kernel<<<dim3(80, 8), blk>>>(word, entity, LL, LW, LE, kw, kb, pK);
    proj_kernel<<<dim3(80, 8), blk>>>(word, entity, LL, LW, LE, vw, vb, pV);
    // gate projections (single-source)
    proj_kernel<<<dim3(64, 8), blk>>>(word,   word,   LW, LW, 0, w2e_qw, w2e_qb, pGQW);
    proj_kernel<<<dim3(16, 8), blk>>>(entity, entity, LE, LE, 0, w2e_kw, w2e_kb, pGKE);
    proj_kernel<<<dim3(16, 8), blk>>>(entity, entity, LE, LE, 0, e2w_qw, e2w_qb, pGQE);
    proj_kernel<<<dim3(64, 8), blk>>>(word,   word,   LW, LW, 0, e2w_kw, e2w_kb, pGKW);

    size_t smem = (size_t)(5 * 64 * SQ + 64 * SP + 64) * sizeof(float); // ~104 KB
    cudaFuncSetAttribute(attn_kernel,
                         cudaFuncAttributeMaxDynamicSharedMemorySize, (int)smem);
    attn_kernel<<<dim3(10, HH, BB), 256, smem>>>(
        pQ, pK, pV, pGQW, pGKW, pGQE, pGKE, mask, (float*)d_out);
}

// round 3
// speedup vs baseline: 1.8116x; 1.8116x over previous
#include <cuda_runtime.h>
#include <cuda_bf16.h>
#include <cstdint>

// ---------------------------------------------------------------------------
// GatedSelfAttention  (B=16, LW=512, LE=128, L=640, D=1024, H=16, DH=64)
// R3: projections via mma.sync bf16 (split hi/lo, 3-term) — base-target ISA
// only (harness compiles compute_103 PTX; tcgen05 unavailable).
// Attention stays fp32 f32x2.
// ---------------------------------------------------------------------------

#define BB   16
#define LW   512
#define LE   128
#define LL   640
#define DD   1024
#define HH   16
#define DHH  64

typedef unsigned long long ull;

// ---------------- f32x2 helpers (attention) ----------------
__device__ __forceinline__ ull pk2(float x, float y) {
    ull r; asm("mov.b64 %0, {%1,%2};" : "=l"(r) : "f"(x), "f"(y)); return r;
}
__device__ __forceinline__ float2 up2(ull v) {
    float2 r; asm("mov.b64 {%0,%1}, %2;" : "=f"(r.x), "=f"(r.y) : "l"(v)); return r;
}
__device__ __forceinline__ void fma2(ull &c, ull a, ull b) {
    asm("fma.rn.f32x2 %0, %1, %2, %0;" : "+l"(c) : "l"(a), "l"(b));
}
__device__ __forceinline__ void mul2(ull &d, ull a, ull b) {
    asm("mul.rn.f32x2 %0, %1, %2;" : "=l"(d) : "l"(a), "l"(b));
}

__device__ __forceinline__ uint32_t smem_u32(const void* p) {
    uint32_t a;
    asm("{ .reg .u64 t; cvta.to.shared.u64 t, %1; cvt.u32.u64 %0, t; }"
        : "=r"(a) : "l"(p));
    return a;
}

// ---------------- mma.sync / ldmatrix / cp.async helpers ----------------
#define LDX4(r, addr) \
    asm volatile("ldmatrix.sync.aligned.m8n8.x4.shared.b16 {%0,%1,%2,%3}, [%4];" \
        : "=r"((r)[0]), "=r"((r)[1]), "=r"((r)[2]), "=r"((r)[3]) : "r"(addr))

__device__ __forceinline__ void mma16816(float* c, const uint32_t* a,
                                         uint32_t b0, uint32_t b1) {
    asm volatile(
        "mma.sync.aligned.m16n8k16.row.col.f32.bf16.bf16.f32 "
        "{%0,%1,%2,%3}, {%4,%5,%6,%7}, {%8,%9}, {%0,%1,%2,%3};"
        : "+f"(c[0]), "+f"(c[1]), "+f"(c[2]), "+f"(c[3])
        : "r"(a[0]), "r"(a[1]), "r"(a[2]), "r"(a[3]), "r"(b0), "r"(b1));
}

__device__ __forceinline__ void cpa16(uint32_t s, const void* g) {
    asm volatile("cp.async.cg.shared.global [%0], [%1], 16;" :: "r"(s), "l"(g));
}
#define CP_COMMIT() asm volatile("cp.async.commit_group;" ::: "memory")
#define CP_WAIT(n)  asm volatile("cp.async.wait_group %0;" :: "n"(n) : "memory")

// ---------------------------------------------------------------------------
// Scratch (device globals; allocation-free)
// ---------------------------------------------------------------------------
__device__ float g_Q  [BB * HH * LL * DHH];
__device__ float g_K  [BB * HH * LL * DHH];
__device__ float g_V  [BB * HH * LL * DHH];
__device__ float g_GQW[BB * HH * LW * DHH];
__device__ float g_GKW[BB * HH * LW * DHH];
__device__ float g_GQE[BB * HH * LE * DHH];
__device__ float g_GKE[BB * HH * LE * DHH];

__device__ __nv_bfloat16 g_Xhi[BB * LL * DD];
__device__ __nv_bfloat16 g_Xlo[BB * LL * DD];
__device__ __nv_bfloat16 g_Whi[7 * DD * DD];   // transposed [N][K]
__device__ __nv_bfloat16 g_Wlo[7 * DD * DD];

__device__ __forceinline__ unsigned short bfbits(__nv_bfloat16 h) {
    return *reinterpret_cast<unsigned short*>(&h);
}

// ---------------------------------------------------------------------------
// Split activations: word+entity fp32 -> concat [10240][1024] bf16 hi/lo
// ---------------------------------------------------------------------------
__global__ __launch_bounds__(256) void split_act(
    const float* __restrict__ word, const float* __restrict__ entity,
    __nv_bfloat16* __restrict__ hi, __nv_bfloat16* __restrict__ lo)
{
    int gid = blockIdx.x * 256 + threadIdx.x;
    int row = gid >> 8;
    int q   = gid & 255;
    int b = row / LL, l = row % LL;
    const float* src = (l < LW)
        ? word   + ((size_t)b * LW + l) * DD + q * 4
        : entity + ((size_t)b * LE + (l - LW)) * DD + q * 4;
    float4 x = *(const float4*)src;
    float xs[4] = {x.x, x.y, x.z, x.w};
    unsigned short hb[4], lb[4];
#pragma unroll
    for (int i = 0; i < 4; i++) {
        __nv_bfloat16 h = __float2bfloat16_rn(xs[i]);
        __nv_bfloat16 lv = __float2bfloat16_rn(xs[i] - __bfloat162float(h));
        hb[i] = bfbits(h); lb[i] = bfbits(lv);
    }
    uint2 uh = { (uint32_t)hb[0] | ((uint32_t)hb[1] << 16),
                 (uint32_t)hb[2] | ((uint32_t)hb[3] << 16) };
    uint2 ul = { (uint32_t)lb[0] | ((uint32_t)lb[1] << 16),
                 (uint32_t)lb[2] | ((uint32_t)lb[3] << 16) };
    *(uint2*)(hi + (size_t)row * DD + q * 4) = uh;
    *(uint2*)(lo + (size_t)row * DD + q * 4) = ul;
}

// ---------------------------------------------------------------------------
// Split + transpose weights: W[K][N] fp32 -> Wt[N][K] bf16 hi/lo (7 weights)
// ---------------------------------------------------------------------------
__global__ __launch_bounds__(256) void split_wt(
    const float* w0, const float* w1, const float* w2, const float* w3,
    const float* w4, const float* w5, const float* w6,
    __nv_bfloat16* __restrict__ hi, __nv_bfloat16* __restrict__ lo)
{
    __shared__ float tile[32][33];
    const float* ws[7] = {w0, w1, w2, w3, w4, w5, w6};
    const float* W = ws[blockIdx.z];
    __nv_bfloat16* H = hi + (size_t)blockIdx.z * DD * DD;
    __nv_bfloat16* L = lo + (size_t)blockIdx.z * DD * DD;

    int k0 = blockIdx.y * 32, n0 = blockIdx.x * 32;
    int tx = threadIdx.x, ty = threadIdx.y;
#pragma unroll
    for (int j = 0; j < 4; j++)
        tile[ty + 8 * j][tx] = W[(size_t)(k0 + ty + 8 * j) * DD + n0 + tx];
    __syncthreads();
#pragma unroll
    for (int j = 0; j < 4; j++) {
        int r = ty + 8 * j;
        float v = tile[tx][r];
        __nv_bfloat16 h = __float2bfloat16_rn(v);
        __nv_bfloat16 lv = __float2bfloat16_rn(v - __bfloat162float(h));
        size_t off = (size_t)(n0 + r) * DD + k0 + tx;
        H[off] = h; L[off] = lv;
    }
}

// ---------------------------------------------------------------------------
// HMMA projection GEMM: out[b,h,l,dh] = X @ W + bias   (split-bf16, 3-term)
// CTA 128x128, K-chunk 32, cp.async double-buffered.
// SMEM per buffer: 4 parts x [128 rows x 80B] (32 bf16 + 16B pad) = 40 KB.
// ---------------------------------------------------------------------------
#define PPART 10240u
#define PBUF  40960u

__global__ __launch_bounds__(256, 2) void proj_mma(
    const __nv_bfloat16* __restrict__ Xhi, const __nv_bfloat16* __restrict__ Xlo,
    const __nv_bfloat16* __restrict__ Whi, const __nv_bfloat16* __restrict__ Wlo,
    const float* __restrict__ bias, float* __restrict__ out,
    int Lx, int rowOff)
{
    extern __shared__ char smc[];
    const uint32_t smb = smem_u32(smc);

    const int tid  = threadIdx.x;
    const int wid  = tid >> 5;
    const int lane = tid & 31;
    const int wm = wid >> 2;         // 0..1  (M)
    const int wn = wid & 3;          // 0..3  (N)

    const int mBase = blockIdx.x * 128;
    const int nBase = blockIdx.y * 128;
    const int b  = mBase / Lx;
    const int l0 = mBase % Lx;

    const __nv_bfloat16* Ah = Xhi + ((size_t)b * LL + rowOff + l0) * DD;
    const __nv_bfloat16* Al = Xlo + ((size_t)b * LL + rowOff + l0) * DD;
    const __nv_bfloat16* Bh = Whi + (size_t)nBase * DD;
    const __nv_bfloat16* Bl = Wlo + (size_t)nBase * DD;
    const __nv_bfloat16* srcs[4] = {Ah, Al, Bh, Bl};

    // loader mapping: 2 x 16B units per thread per part
    const int u0   = tid * 2;
    const int lrow = u0 >> 2;        // 0..127
    const int lcol = u0 & 3;         // 0 or 2

    // ldmatrix lane offsets
    const uint32_t a_off =
        (uint32_t)((wm * 64 + (lane & 15)) * 80 + (lane >> 4) * 16);
    const uint32_t b_off =
        (uint32_t)((wn * 32 + (lane & 7) + ((lane >> 4) & 1) * 8) * 80 +
                   ((lane >> 3) & 1) * 16);

    float acc[4][4][4];
#pragma unroll
    for (int mt = 0; mt < 4; mt++)
#pragma unroll
        for (int nt = 0; nt < 4; nt++)
#pragma unroll
            for (int i = 0; i < 4; i++) acc[mt][nt][i] = 0.0f;

    // prefetch chunk 0
    {
        const int k0 = 0;
#pragma unroll
        for (int p = 0; p < 4; p++) {
            const __nv_bfloat16* gp = srcs[p] + (size_t)lrow * DD + k0 + lcol * 8;
            uint32_t sp = smb + p * PPART + (uint32_t)(lrow * 80 + lcol * 16);
            cpa16(sp, gp);
            cpa16(sp + 16, gp + 8);
        }
        CP_COMMIT();
    }

    for (int c = 0; c < 32; c++) {
        const int buf = c & 1;
        if (c + 1 < 32) {
            const int k0 = (c + 1) * 32;
            const uint32_t bb = (uint32_t)(buf ^ 1) * PBUF;
#pragma unroll
            for (int p = 0; p < 4; p++) {
                const __nv_bfloat16* gp = srcs[p] + (size_t)lrow * DD + k0 + lcol * 8;
                uint32_t sp = smb + bb + p * PPART + (uint32_t)(lrow * 80 + lcol * 16);
                cpa16(sp, gp);
                cpa16(sp + 16, gp + 8);
            }
            CP_COMMIT();
            CP_WAIT(1);
        } else {
            CP_WAIT(0);
        }
        __syncthreads();

        const uint32_t base = smb + (uint32_t)buf * PBUF;
#pragma unroll
        for (int k16 = 0; k16 < 2; k16++) {
            const uint32_t kb = (uint32_t)k16 * 32;
            uint32_t ah[4][4], bh[2][4], bl[2][4], al[4][4];
            // A-hi fragments
#pragma unroll
            for (int mt = 0; mt < 4; mt++)
                LDX4(ah[mt], base + 0 * PPART + a_off + (uint32_t)(mt * 16 * 80) + kb);
            // B-hi fragments
#pragma unroll
            for (int np = 0; np < 2; np++)
                LDX4(bh[np], base + 2 * PPART + b_off + (uint32_t)(np * 16 * 80) + kb);
            // pass hh
#pragma unroll
            for (int mt = 0; mt < 4; mt++)
#pragma unroll
                for (int nt = 0; nt < 4; nt++)
                    mma16816(acc[mt][nt], ah[mt], bh[nt >> 1][(nt & 1) * 2],
                             bh[nt >> 1][(nt & 1) * 2 + 1]);
            // B-lo fragments, pass hl
#pragma unroll
            for (int np = 0; np < 2; np++)
                LDX4(bl[np], base + 3 * PPART + b_off + (uint32_t)(np * 16 * 80) + kb);
#pragma unroll
            for (int mt = 0; mt < 4; mt++)
#pragma unroll
                for (int nt = 0; nt < 4; nt++)
                    mma16816(acc[mt][nt], ah[mt], bl[nt >> 1][(nt & 1) * 2],
                             bl[nt >> 1][(nt & 1) * 2 + 1]);
            // A-lo fragments, pass lh
#pragma unroll
            for (int mt = 0; mt < 4; mt++)
                LDX4(al[mt], base + 1 * PPART + a_off + (uint32_t)(mt * 16 * 80) + kb);
#pragma unroll
            for (int mt = 0; mt < 4; mt++)
#pragma unroll
                for (int nt = 0; nt < 4; nt++)
                    mma16816(acc[mt][nt], al[mt], bh[nt >> 1][(nt & 1) * 2],
                             bh[nt >> 1][(nt & 1) * 2 + 1]);
        }
        __syncthreads();
    }

    // epilogue: bias add, head-major store
#pragma unroll
    for (int mt = 0; mt < 4; mt++) {
        const int lloc = l0 + wm * 64 + mt * 16 + (lane >> 2);
#pragma unroll
        for (int nt = 0; nt < 4; nt++) {
            const int n  = nBase + wn * 32 + nt * 8 + (lane & 3) * 2;
            const int h  = n >> 6;
            const int dh = n & 63;
            const float bx = bias[n], by = bias[n + 1];
            float* o = out + (((size_t)b * HH + h) * Lx + lloc) * DHH + dh;
            float2 r0 = {acc[mt][nt][0] + bx, acc[mt][nt][1] + by};
            float2 r1 = {acc[mt][nt][2] + bx, acc[mt][nt][3] + by};
            *(float2*)o = r0;
            *(float2*)(o + 8 * DHH) = r1;
        }
    }
}

// ---------------------------------------------------------------------------
// Fused attention (unchanged): per (b, h, 64-row q tile)
// ---------------------------------------------------------------------------
#define SQ 68
#define SP 65

__global__ __launch_bounds__(256, 2) void attn_kernel(
    const float* __restrict__ Q, const float* __restrict__ K, const float* __restrict__ V,
    const float* __restrict__ GQW, const float* __restrict__ GKW,
    const float* __restrict__ GQE, const float* __restrict__ GKE,
    const float* __restrict__ mask, float* __restrict__ out)
{
    extern __shared__ float smf[];
    float* Qt    = smf;
    float* Gqt   = Qt  + 64 * SQ;
    float* Kt    = Gqt + 64 * SQ;
    float* Gkt   = Kt  + 64 * SQ;
    float* Vs    = Gkt + 64 * SQ;
    float* Ps    = Vs  + 64 * SQ;
    float* maskS = Ps  + 64 * SP;

    const int tid = threadIdx.x;
    const int qt  = blockIdx.x;
    const int h   = blockIdx.y;
    const int b   = blockIdx.z;
    const int q0  = qt * 64;
    const bool qWord = (q0 < LW);
    const int ty = tid >> 4, tx = tid & 15;

    const size_t bh = (size_t)(b * HH + h);
    const float* Qsrc  = Q + (bh * LL + q0) * DHH;
    const float* gqsrc = qWord ? GQW + (bh * LW + q0) * DHH
                               : GQE + (bh * LE + (q0 - LW)) * DHH;

    {
        const int j  = tid & 63;
        const int dg = (tid >> 6) * 16;
        const float* s = Qsrc  + j * DHH + dg;
        const float* g = gqsrc + j * DHH + dg;
#pragma unroll
        for (int c = 0; c < 16; c += 4) {
            float4 v = *(const float4*)(s + c);
            Qt[(dg + c + 0) * SQ + j] = v.x;
            Qt[(dg + c + 1) * SQ + j] = v.y;
            Qt[(dg + c + 2) * SQ + j] = v.z;
            Qt[(dg + c + 3) * SQ + j] = v.w;
            float4 w = *(const float4*)(g + c);
            Gqt[(dg + c + 0) * SQ + j] = w.x;
            Gqt[(dg + c + 1) * SQ + j] = w.y;
            Gqt[(dg + c + 2) * SQ + j] = w.z;
            Gqt[(dg + c + 3) * SQ + j] = w.w;
        }
    }

    ull o2[4][2];
    float m_run[4], l_run[4];
#pragma unroll
    for (int r = 0; r < 4; r++) {
        o2[r][0] = 0ULL; o2[r][1] = 0ULL;
        m_run[r] = -1e30f; l_run[r] = 0.0f;
    }

    for (int kt = 0; kt < 10; kt++) {
        const int  k0    = kt * 64;
        const bool kWord = (k0 < LW);
        const bool cross = (kWord != qWord);

        __syncthreads();

        {
            const int j  = tid & 63;
            const int dg = (tid >> 6) * 16;
            const float* s = K + (bh * LL + k0 + j) * DHH + dg;
#pragma unroll
            for (int c = 0; c < 16; c += 4) {
                float4 v = *(const float4*)(s + c);
                Kt[(dg + c + 0) * SQ + j] = v.x;
                Kt[(dg + c + 1) * SQ + j] = v.y;
                Kt[(dg + c + 2) * SQ + j] = v.z;
                Kt[(dg + c + 3) * SQ + j] = v.w;
            }
            if (cross) {
                const float* g = qWord
                    ? GKE + (bh * LE + (k0 - LW) + j) * DHH + dg
                    : GKW + (bh * LW +  k0       + j) * DHH + dg;
#pragma unroll
                for (int c = 0; c < 16; c += 4) {
                    float4 w = *(const float4*)(g + c);
                    Gkt[(dg + c + 0) * SQ + j] = w.x;
                    Gkt[(dg + c + 1) * SQ + j] = w.y;
                    Gkt[(dg + c + 2) * SQ + j] = w.z;
                    Gkt[(dg + c + 3) * SQ + j] = w.w;
                }
            }
        }
#pragma unroll
        for (int it = 0; it < 4; it++) {
            int idx = tid + it * 256;
            int row = idx >> 4;
            int cg  = (idx & 15) * 4;
            float4 v = *(const float4*)(V + (bh * LL + k0 + row) * DHH + cg);
            *(float4*)&Vs[row * SQ + cg] = v;
        }
        if (tid < 16) {
            float4 mv = *(const float4*)(mask + (size_t)b * LL + k0 + tid * 4);
            *(float4*)&maskS[tid * 4] = mv;
        }
        __syncthreads();

        ull s2[4][2] = {{0ULL,0ULL},{0ULL,0ULL},{0ULL,0ULL},{0ULL,0ULL}};
        ull g2[4][2] = {{0ULL,0ULL},{0ULL,0ULL},{0ULL,0ULL},{0ULL,0ULL}};
        if (cross) {
#pragma unroll 2
            for (int d = 0; d < 64; d++) {
                float4 qv = *(const float4*)&Qt [d * SQ + ty * 4];
                float4 kv = *(const float4*)&Kt [d * SQ + tx * 4];
                float4 gq = *(const float4*)&Gqt[d * SQ + ty * 4];
                float4 gk = *(const float4*)&Gkt[d * SQ + tx * 4];
                ull k01 = pk2(kv.x, kv.y), k23 = pk2(kv.z, kv.w);
                ull e01 = pk2(gk.x, gk.y), e23 = pk2(gk.z, gk.w);
                float qa[4] = {qv.x, qv.y, qv.z, qv.w};
                float ga[4] = {gq.x, gq.y, gq.z, gq.w};
#pragma unroll
                for (int r = 0; r < 4; r++) {
                    ull qd = pk2(qa[r], qa[r]);
                    fma2(s2[r][0], qd, k01);
                    fma2(s2[r][1], qd, k23);
                    ull gd = pk2(ga[r], ga[r]);
                    fma2(g2[r][0], gd, e01);
                    fma2(g2[r][1], gd, e23);
                }
            }
        } else {
#pragma unroll 4
            for (int d = 0; d < 64; d++) {
                float4 qv = *(const float4*)&Qt[d * SQ + ty * 4];
                float4 kv = *(const float4*)&Kt[d * SQ + tx * 4];
                ull k01 = pk2(kv.x, kv.y), k23 = pk2(kv.z, kv.w);
                float qa[4] = {qv.x, qv.y, qv.z, qv.w};
#pragma unroll
                for (int r = 0; r < 4; r++) {
                    ull qd = pk2(qa[r], qa[r]);
                    fma2(s2[r][0], qd, k01);
                    fma2(s2[r][1], qd, k23);
                }
            }
        }

        float p[4][4];
#pragma unroll
        for (int r = 0; r < 4; r++) {
            float2 u0 = up2(s2[r][0]);
            float2 u1 = up2(s2[r][1]);
            float sv[4] = {u0.x, u0.y, u1.x, u1.y};
            if (cross) {
                float2 w0 = up2(g2[r][0]);
                float2 w1 = up2(g2[r][1]);
                float gv[4] = {w0.x, w0.y, w1.x, w1.y};
#pragma unroll
                for (int c = 0; c < 4; c++)
                    sv[c] += -10.0f / (1.0f + __expf(-gv[c]));
            } else {
#pragma unroll
                for (int c = 0; c < 4; c++) sv[c] -= 5.0f;
            }
#pragma unroll
            for (int c = 0; c < 4; c++)
                sv[c] = sv[c] * 0.125f + maskS[tx * 4 + c];

            float mr = fmaxf(fmaxf(sv[0], sv[1]), fmaxf(sv[2], sv[3]));
#pragma unroll
            for (int off = 8; off >= 1; off >>= 1)
                mr = fmaxf(mr, __shfl_xor_sync(0xffffffffu, mr, off));
            float mnew = fmaxf(m_run[r], mr);
            float corr = __expf(m_run[r] - mnew);
            m_run[r] = mnew;
            float rs = 0.0f;
#pragma unroll
            for (int c = 0; c < 4; c++) {
                p[r][c] = __expf(sv[c] - mnew);
                rs += p[r][c];
            }
#pragma unroll
            for (int off = 8; off >= 1; off >>= 1)
                rs += __shfl_xor_sync(0xffffffffu, rs, off);
            l_run[r] = l_run[r] * corr + rs;
            ull cd = pk2(corr, corr);
            mul2(o2[r][0], o2[r][0], cd);
            mul2(o2[r][1], o2[r][1], cd);
        }

#pragma unroll
        for (int r = 0; r < 4; r++)
#pragma unroll
            for (int c = 0; c < 4; c++)
                Ps[(ty * 4 + r) * SP + tx * 4 + c] = p[r][c];
        __syncthreads();

#pragma unroll 4
        for (int kk = 0; kk < 64; kk++) {
            float4 vv = *(const float4*)&Vs[kk * SQ + tx * 4];
            ull v01 = pk2(vv.x, vv.y), v23 = pk2(vv.z, vv.w);
#pragma unroll
            for (int r = 0; r < 4; r++) {
                float pr = Ps[(ty * 4 + r) * SP + kk];
                ull pd = pk2(pr, pr);
                fma2(o2[r][0], pd, v01);
                fma2(o2[r][1], pd, v23);
            }
        }
    }

#pragma unroll
    for (int r = 0; r < 4; r++) {
        float inv = 1.0f / l_run[r];
        float2 a0 = up2(o2[r][0]);
        float2 a1 = up2(o2[r][1]);
        float4 o = {a0.x * inv, a0.y * inv, a1.x * inv, a1.y * inv};
        int q = q0 + ty * 4 + r;
        size_t off;
        if (q < LW)
            off = ((size_t)b * LW + q) * DD + h * DHH + tx * 4;
        else
            off = (size_t)BB * LW * DD +
                  ((size_t)b * LE + (q - LW)) * DD + h * DHH + tx * 4;
        *(float4*)(out + off) = o;
    }
}

// ---------------------------------------------------------------------------
// Launch
// ---------------------------------------------------------------------------
extern "C" void kernel_launch(void* const* d_in, const int* in_sizes, int n_in,
                              void* d_out, int out_size)
{
    const float* word   = (const float*)d_in[0];
    const float* entity = (const float*)d_in[1];
    const float* mask   = (const float*)d_in[2];
    int base = (in_sizes[3] == 1) ? 4 : 3;
    const float* qw     = (const float*)d_in[base + 0];
    const float* qb     = (const float*)d_in[base + 1];
    const float* kw     = (const float*)d_in[base + 2];
    const float* kb     = (const float*)d_in[base + 3];
    const float* vw     = (const float*)d_in[base + 4];
    const float* vb     = (const float*)d_in[base + 5];
    const float* w2e_qw = (const float*)d_in[base + 6];
    const float* w2e_qb = (const float*)d_in[base + 7];
    const float* w2e_kw = (const float*)d_in[base + 8];
    const float* w2e_kb = (const float*)d_in[base + 9];
    const float* e2w_qw = (const float*)d_in[base + 10];
    const float* e2w_qb = (const float*)d_in[base + 11];
    const float* e2w_kw = (const float*)d_in[base + 12];
    const float* e2w_kb = (const float*)d_in[base + 13];

    float *pQ, *pK, *pV, *pGQW, *pGKW, *pGQE, *pGKE;
    __nv_bfloat16 *pXhi, *pXlo, *pWhi, *pWlo;
    cudaGetSymbolAddress((void**)&pQ,   g_Q);
    cudaGetSymbolAddress((void**)&pK,   g_K);
    cudaGetSymbolAddress((void**)&pV,   g_V);
    cudaGetSymbolAddress((void**)&pGQW, g_GQW);
    cudaGetSymbolAddress((void**)&pGKW, g_GKW);
    cudaGetSymbolAddress((void**)&pGQE, g_GQE);
    cudaGetSymbolAddress((void**)&pGKE, g_GKE);
    cudaGetSymbolAddress((void**)&pXhi, g_Xhi);
    cudaGetSymbolAddress((void**)&pXlo, g_Xlo);
    cudaGetSymbolAddress((void**)&pWhi, g_Whi);
    cudaGetSymbolAddress((void**)&pWlo, g_Wlo);

    // ---- split pass ----
    split_act<<<BB * LL, 256>>>(word, entity, pXhi, pXlo);
    split_wt<<<dim3(32, 32, 7), dim3(32, 8)>>>(
        qw, kw, vw, w2e_qw, w2e_kw, e2w_qw, e2w_kw, pWhi, pWlo);

    // ---- HMMA projections ----
    const size_t psmem = 2 * PBUF;   // 80 KB
    cudaFuncSetAttribute(proj_mma,
                         cudaFuncAttributeMaxDynamicSharedMemorySize, (int)psmem);
    const size_t WSZ = (size_t)DD * DD;
    proj_mma<<<dim3(80, 8), 256, psmem>>>(pXhi, pXlo, pWhi + 0 * WSZ, pWlo + 0 * WSZ, qb,     pQ,   LL, 0);
    proj_mma<<<dim3(80, 8), 256, psmem>>>(pXhi, pXlo, pWhi + 1 * WSZ, pWlo + 1 * WSZ, kb,     pK,   LL, 0);
    proj_mma<<<dim3(80, 8), 256, psmem>>>(pXhi, pXlo, pWhi + 2 * WSZ, pWlo + 2 * WSZ, vb,     pV,   LL, 0);
    proj_mma<<<dim3(64, 8), 256, psmem>>>(pXhi, pXlo, pWhi + 3 * WSZ, pWlo + 3 * WSZ, w2e_qb, pGQW, LW, 0);
    proj_mma<<<dim3(16, 8), 256, psmem>>>(pXhi, pXlo, pWhi + 4 * WSZ, pWlo + 4 * WSZ, w2e_kb, pGKE, LE, LW);
    proj_mma<<<dim3(16, 8), 256, psmem>>>(pXhi, pXlo, pWhi + 5 * WSZ, pWlo + 5 * WSZ, e2w_qb, pGQE, LE, LW);
    proj_mma<<<dim3(64, 8), 256, psmem>>>(pXhi, pXlo, pWhi + 6 * WSZ, pWlo + 6 * WSZ, e2w_kb, pGKW, LW, 0);

    // ---- attention ----
    size_t asmem = (size_t)(5 * 64 * SQ + 64 * SP + 64) * sizeof(float);
    cudaFuncSetAttribute(attn_kernel,
                         cudaFuncAttributeMaxDynamicSharedMemorySize, (int)asmem);
    attn_kernel<<<dim3(10, HH, BB), 256, asmem>>>(
        pQ, pK, pV, pGQW, pGKW, pGQE, pGKE, mask, (float*)d_out);
}

// round 5
// speedup vs baseline: 2.6109x; 1.4412x over previous
#include <cuda_runtime.h>
#include <cuda_bf16.h>
#include <cstdint>

// ---------------------------------------------------------------------------
// GatedSelfAttention  (B=16, LW=512, LE=128, L=640, D=1024, H=16, DH=64)
// R5: R4 with the smem staging bug fixed (all tiles were staged at 50%).
// Projections AND attention via mma.sync bf16 split hi/lo (3-term).
// ---------------------------------------------------------------------------

#define BB   16
#define LW   512
#define LE   128
#define LL   640
#define DD   1024
#define HH   16
#define DHH  64

typedef unsigned long long ull;
typedef __nv_bfloat16 bf16;

__device__ __forceinline__ uint32_t smem_u32(const void* p) {
    uint32_t a;
    asm("{ .reg .u64 t; cvta.to.shared.u64 t, %1; cvt.u32.u64 %0, t; }"
        : "=r"(a) : "l"(p));
    return a;
}

// ---------------- mma.sync / ldmatrix / cp.async helpers ----------------
#define LDX4(r, addr) \
    asm volatile("ldmatrix.sync.aligned.m8n8.x4.shared.b16 {%0,%1,%2,%3}, [%4];" \
        : "=r"((r)[0]), "=r"((r)[1]), "=r"((r)[2]), "=r"((r)[3]) : "r"(addr))

__device__ __forceinline__ void mma16816(float* c, const uint32_t* a,
                                         uint32_t b0, uint32_t b1) {
    asm volatile(
        "mma.sync.aligned.m16n8k16.row.col.f32.bf16.bf16.f32 "
        "{%0,%1,%2,%3}, {%4,%5,%6,%7}, {%8,%9}, {%0,%1,%2,%3};"
        : "+f"(c[0]), "+f"(c[1]), "+f"(c[2]), "+f"(c[3])
        : "r"(a[0]), "r"(a[1]), "r"(a[2]), "r"(a[3]), "r"(b0), "r"(b1));
}

__device__ __forceinline__ void cpa16(uint32_t s, const void* g) {
    asm volatile("cp.async.cg.shared.global [%0], [%1], 16;" :: "r"(s), "l"(g));
}
#define CP_COMMIT() asm volatile("cp.async.commit_group;" ::: "memory")
#define CP_WAIT(n)  asm volatile("cp.async.wait_group %0;" :: "n"(n) : "memory")

__device__ __forceinline__ unsigned short bfbits(bf16 h) {
    return *reinterpret_cast<unsigned short*>(&h);
}
__device__ __forceinline__ void bsplit(float v, unsigned short &h, unsigned short &l) {
    bf16 bh_ = __float2bfloat16_rn(v);
    bf16 bl_ = __float2bfloat16_rn(v - __bfloat162float(bh_));
    h = bfbits(bh_); l = bfbits(bl_);
}

// ---------------------------------------------------------------------------
// Scratch (device globals; allocation-free)
// ---------------------------------------------------------------------------
__device__ bf16 g_Qh  [BB*HH*LL*DHH],  g_Ql  [BB*HH*LL*DHH];
__device__ bf16 g_Kh  [BB*HH*LL*DHH],  g_Kl  [BB*HH*LL*DHH];
__device__ bf16 g_Vth [BB*HH*DHH*LL],  g_Vtl [BB*HH*DHH*LL];   // transposed [bh][dh][L]
__device__ bf16 g_GQWh[BB*HH*LW*DHH],  g_GQWl[BB*HH*LW*DHH];
__device__ bf16 g_GKWh[BB*HH*LW*DHH],  g_GKWl[BB*HH*LW*DHH];
__device__ bf16 g_GQEh[BB*HH*LE*DHH],  g_GQEl[BB*HH*LE*DHH];
__device__ bf16 g_GKEh[BB*HH*LE*DHH],  g_GKEl[BB*HH*LE*DHH];

__device__ bf16 g_Xhi[BB*LL*DD], g_Xlo[BB*LL*DD];
__device__ bf16 g_Whi[7*DD*DD],  g_Wlo[7*DD*DD];     // weights transposed [N][K]

// ---------------------------------------------------------------------------
// Split activations: word+entity fp32 -> concat [10240][1024] bf16 hi/lo
// ---------------------------------------------------------------------------
__global__ __launch_bounds__(256) void split_act(
    const float* __restrict__ word, const float* __restrict__ entity,
    bf16* __restrict__ hi, bf16* __restrict__ lo)
{
    int gid = blockIdx.x * 256 + threadIdx.x;
    int row = gid >> 8;
    int q   = gid & 255;
    int b = row / LL, l = row % LL;
    const float* src = (l < LW)
        ? word   + ((size_t)b * LW + l) * DD + q * 4
        : entity + ((size_t)b * LE + (l - LW)) * DD + q * 4;
    float4 x = *(const float4*)src;
    float xs[4] = {x.x, x.y, x.z, x.w};
    unsigned short hb[4], lb[4];
#pragma unroll
    for (int i = 0; i < 4; i++) bsplit(xs[i], hb[i], lb[i]);
    uint2 uh = { (uint32_t)hb[0] | ((uint32_t)hb[1] << 16),
                 (uint32_t)hb[2] | ((uint32_t)hb[3] << 16) };
    uint2 ul = { (uint32_t)lb[0] | ((uint32_t)lb[1] << 16),
                 (uint32_t)lb[2] | ((uint32_t)lb[3] << 16) };
    *(uint2*)(hi + (size_t)row * DD + q * 4) = uh;
    *(uint2*)(lo + (size_t)row * DD + q * 4) = ul;
}

// ---------------------------------------------------------------------------
// Split + transpose weights: W[K][N] fp32 -> Wt[N][K] bf16 hi/lo (7 weights)
// ---------------------------------------------------------------------------
__global__ __launch_bounds__(256) void split_wt(
    const float* w0, const float* w1, const float* w2, const float* w3,
    const float* w4, const float* w5, const float* w6,
    bf16* __restrict__ hi, bf16* __restrict__ lo)
{
    __shared__ float tile[32][33];
    const float* ws[7] = {w0, w1, w2, w3, w4, w5, w6};
    const float* W = ws[blockIdx.z];
    bf16* H = hi + (size_t)blockIdx.z * DD * DD;
    bf16* L = lo + (size_t)blockIdx.z * DD * DD;

    int k0 = blockIdx.y * 32, n0 = blockIdx.x * 32;
    int tx = threadIdx.x, ty = threadIdx.y;
#pragma unroll
    for (int j = 0; j < 4; j++)
        tile[ty + 8 * j][tx] = W[(size_t)(k0 + ty + 8 * j) * DD + n0 + tx];
    __syncthreads();
#pragma unroll
    for (int j = 0; j < 4; j++) {
        int r = ty + 8 * j;
        unsigned short hb, lb;
        bsplit(tile[tx][r], hb, lb);
        size_t off = (size_t)(n0 + r) * DD + k0 + tx;
        H[off] = *reinterpret_cast<bf16*>(&hb);
        L[off] = *reinterpret_cast<bf16*>(&lb);
    }
}

// ---------------------------------------------------------------------------
// HMMA projection GEMM (split-bf16, 3-term). Outputs bf16 hi/lo.
// vtrans=0: out [bh][Lx][64];  vtrans=1: out [bh][64][Lx] (for V).
// ---------------------------------------------------------------------------
#define PPART 10240u
#define PBUF  40960u

__global__ __launch_bounds__(256, 2) void proj_mma(
    const bf16* __restrict__ Xhi, const bf16* __restrict__ Xlo,
    const bf16* __restrict__ Whi, const bf16* __restrict__ Wlo,
    const float* __restrict__ bias,
    bf16* __restrict__ outHi, bf16* __restrict__ outLo,
    int Lx, int rowOff, int vtrans)
{
    extern __shared__ char smc[];
    const uint32_t smb = smem_u32(smc);

    const int tid  = threadIdx.x;
    const int wid  = tid >> 5;
    const int lane = tid & 31;
    const int wm = wid >> 2;
    const int wn = wid & 3;

    const int mBase = blockIdx.x * 128;
    const int nBase = blockIdx.y * 128;
    const int b  = mBase / Lx;
    const int l0 = mBase % Lx;

    const bf16* Ah = Xhi + ((size_t)b * LL + rowOff + l0) * DD;
    const bf16* Al = Xlo + ((size_t)b * LL + rowOff + l0) * DD;
    const bf16* Bh = Whi + (size_t)nBase * DD;
    const bf16* Bl = Wlo + (size_t)nBase * DD;
    const bf16* srcs[4] = {Ah, Al, Bh, Bl};

    const int u0   = tid * 2;
    const int lrow = u0 >> 2;
    const int lcol = u0 & 3;

    const uint32_t a_off =
        (uint32_t)((wm * 64 + (lane & 15)) * 80 + (lane >> 4) * 16);
    const uint32_t b_off =
        (uint32_t)((wn * 32 + (lane & 7) + ((lane >> 4) & 1) * 8) * 80 +
                   ((lane >> 3) & 1) * 16);

    float acc[4][4][4];
#pragma unroll
    for (int mt = 0; mt < 4; mt++)
#pragma unroll
        for (int nt = 0; nt < 4; nt++)
#pragma unroll
            for (int i = 0; i < 4; i++) acc[mt][nt][i] = 0.0f;

    {
#pragma unroll
        for (int p = 0; p < 4; p++) {
            const bf16* gp = srcs[p] + (size_t)lrow * DD + lcol * 8;
            uint32_t sp = smb + p * PPART + (uint32_t)(lrow * 80 + lcol * 16);
            cpa16(sp, gp);
            cpa16(sp + 16, gp + 8);
        }
        CP_COMMIT();
    }

    for (int c = 0; c < 32; c++) {
        const int buf = c & 1;
        if (c + 1 < 32) {
            const int k0 = (c + 1) * 32;
            const uint32_t bb = (uint32_t)(buf ^ 1) * PBUF;
#pragma unroll
            for (int p = 0; p < 4; p++) {
                const bf16* gp = srcs[p] + (size_t)lrow * DD + k0 + lcol * 8;
                uint32_t sp = smb + bb + p * PPART + (uint32_t)(lrow * 80 + lcol * 16);
                cpa16(sp, gp);
                cpa16(sp + 16, gp + 8);
            }
            CP_COMMIT();
            CP_WAIT(1);
        } else {
            CP_WAIT(0);
        }
        __syncthreads();

        const uint32_t base = smb + (uint32_t)buf * PBUF;
#pragma unroll
        for (int k16 = 0; k16 < 2; k16++) {
            const uint32_t kb = (uint32_t)k16 * 32;
            uint32_t ah[4][4], bh[2][4], bl[2][4], al[4][4];
#pragma unroll
            for (int mt = 0; mt < 4; mt++)
                LDX4(ah[mt], base + 0 * PPART + a_off + (uint32_t)(mt * 16 * 80) + kb);
#pragma unroll
            for (int np = 0; np < 2; np++)
                LDX4(bh[np], base + 2 * PPART + b_off + (uint32_t)(np * 16 * 80) + kb);
#pragma unroll
            for (int mt = 0; mt < 4; mt++)
#pragma unroll
                for (int nt = 0; nt < 4; nt++)
                    mma16816(acc[mt][nt], ah[mt], bh[nt >> 1][(nt & 1) * 2],
                             bh[nt >> 1][(nt & 1) * 2 + 1]);
#pragma unroll
            for (int np = 0; np < 2; np++)
                LDX4(bl[np], base + 3 * PPART + b_off + (uint32_t)(np * 16 * 80) + kb);
#pragma unroll
            for (int mt = 0; mt < 4; mt++)
#pragma unroll
                for (int nt = 0; nt < 4; nt++)
                    mma16816(acc[mt][nt], ah[mt], bl[nt >> 1][(nt & 1) * 2],
                             bl[nt >> 1][(nt & 1) * 2 + 1]);
#pragma unroll
            for (int mt = 0; mt < 4; mt++)
                LDX4(al[mt], base + 1 * PPART + a_off + (uint32_t)(mt * 16 * 80) + kb);
#pragma unroll
            for (int mt = 0; mt < 4; mt++)
#pragma unroll
                for (int nt = 0; nt < 4; nt++)
                    mma16816(acc[mt][nt], al[mt], bh[nt >> 1][(nt & 1) * 2],
                             bh[nt >> 1][(nt & 1) * 2 + 1]);
        }
        __syncthreads();
    }

    // epilogue: bias add, split hi/lo, store
#pragma unroll
    for (int mt = 0; mt < 4; mt++) {
        const int lloc = l0 + wm * 64 + mt * 16 + (lane >> 2);
#pragma unroll
        for (int nt = 0; nt < 4; nt++) {
            const int n  = nBase + wn * 32 + nt * 8 + (lane & 3) * 2;
            const int h  = n >> 6;
            const int dh = n & 63;
            const float bx = bias[n], by = bias[n + 1];
            float v00 = acc[mt][nt][0] + bx, v01 = acc[mt][nt][1] + by;
            float v10 = acc[mt][nt][2] + bx, v11 = acc[mt][nt][3] + by;
            unsigned short h00,l00,h01,l01,h10,l10,h11,l11;
            bsplit(v00,h00,l00); bsplit(v01,h01,l01);
            bsplit(v10,h10,l10); bsplit(v11,h11,l11);
            if (!vtrans) {
                size_t e0 = (((size_t)b * HH + h) * Lx + lloc) * DHH + dh;
                size_t e1 = e0 + 8 * DHH;
                *(uint32_t*)(outHi + e0) = (uint32_t)h00 | ((uint32_t)h01 << 16);
                *(uint32_t*)(outLo + e0) = (uint32_t)l00 | ((uint32_t)l01 << 16);
                *(uint32_t*)(outHi + e1) = (uint32_t)h10 | ((uint32_t)h11 << 16);
                *(uint32_t*)(outLo + e1) = (uint32_t)l10 | ((uint32_t)l11 << 16);
            } else {
                size_t t0 = (((size_t)b * HH + h) * DHH + dh) * Lx + lloc;
                outHi[t0]          = *reinterpret_cast<bf16*>(&h00);
                outLo[t0]          = *reinterpret_cast<bf16*>(&l00);
                outHi[t0 + 8]      = *reinterpret_cast<bf16*>(&h10);
                outLo[t0 + 8]      = *reinterpret_cast<bf16*>(&l10);
                outHi[t0 + Lx]     = *reinterpret_cast<bf16*>(&h01);
                outLo[t0 + Lx]     = *reinterpret_cast<bf16*>(&l01);
                outHi[t0 + Lx + 8] = *reinterpret_cast<bf16*>(&h11);
                outLo[t0 + Lx + 8] = *reinterpret_cast<bf16*>(&l11);
            }
        }
    }
}

// ---------------------------------------------------------------------------
// HMMA fused attention.  CTA = 128 q rows; iterate 10 kv tiles of 64.
// Swizzled smem (SW128 on 128B rows).  Regions (byte offsets):
//   QH 0, QL 16384 | R1 32768, R1L 49152 (Gq -> P) | R2 65536, R2L 73728
//   (Gk -> K) | VH 81920, VL 90112 | mask 98304  (total 98560 B)
// ---------------------------------------------------------------------------
#define SM_QH 0u
#define SM_QL 16384u
#define SM_R1 32768u
#define SM_R1L 49152u
#define SM_R2 65536u
#define SM_R2L 73728u
#define SM_VH 81920u
#define SM_VL 90112u
#define SM_MS 98304u
#define ATT_SMEM 98560u

__device__ __forceinline__ uint32_t swz(uint32_t base, int row, int c16) {
    return base + (uint32_t)(row * 128) + (uint32_t)(((c16 ^ (row & 7)) << 4));
}

// 3-term GEMM tile: acc[8][4] += A(16 rows/warp x 64) * B(64 x 64)
__device__ __forceinline__ void gemm3(
    float (*acc)[4], uint32_t AHb, uint32_t ALb, uint32_t BHb, uint32_t BLb,
    int aRow, int bRow0, int aC, int bC)
{
#pragma unroll
    for (int s = 0; s < 4; s++) {
        uint32_t ah[4], al[4];
        uint32_t aoff = swz(AHb, aRow, 2 * s + aC) - AHb;
        LDX4(ah, AHb + aoff);
        LDX4(al, ALb + aoff);
#pragma unroll
        for (int ntp = 0; ntp < 4; ntp++) {
            int br = bRow0 + ntp * 16;
            uint32_t boff = swz(BHb, br, 2 * s + bC) - BHb;
            uint32_t bhf[4], blf[4];
            LDX4(bhf, BHb + boff);
            mma16816(acc[2*ntp],   ah, bhf[0], bhf[1]);
            mma16816(acc[2*ntp+1], ah, bhf[2], bhf[3]);
            LDX4(blf, BLb + boff);
            mma16816(acc[2*ntp],   ah, blf[0], blf[1]);
            mma16816(acc[2*ntp+1], ah, blf[2], blf[3]);
            mma16816(acc[2*ntp],   al, bhf[0], bhf[1]);
            mma16816(acc[2*ntp+1], al, bhf[2], bhf[3]);
        }
    }
}

__global__ __launch_bounds__(256, 2) void attn_mma(
    const bf16* __restrict__ Qh,  const bf16* __restrict__ Ql,
    const bf16* __restrict__ Kh,  const bf16* __restrict__ Kl,
    const bf16* __restrict__ Vth, const bf16* __restrict__ Vtl,
    const bf16* __restrict__ GQWh,const bf16* __restrict__ GQWl,
    const bf16* __restrict__ GKWh,const bf16* __restrict__ GKWl,
    const bf16* __restrict__ GQEh,const bf16* __restrict__ GQEl,
    const bf16* __restrict__ GKEh,const bf16* __restrict__ GKEl,
    const float* __restrict__ mask, float* __restrict__ out)
{
    extern __shared__ char smc[];
    const uint32_t smb = smem_u32(smc);

    const int tid  = threadIdx.x;
    const int wid  = tid >> 5;
    const int lane = tid & 31;

    const int qt = blockIdx.x;          // 0..4
    const int h  = blockIdx.y;
    const int b  = blockIdx.z;
    const int q0 = qt * 128;
    const bool qWord = (q0 < LW);
    const size_t bh = (size_t)(b * HH + h);

    const bf16* Qhg = Qh + (bh * LL + q0) * DHH;
    const bf16* Qlg = Ql + (bh * LL + q0) * DHH;
    const bf16* Gqh = qWord ? GQWh + (bh * LW + q0) * DHH
                            : GQEh + (bh * LE + (q0 - LW)) * DHH;
    const bf16* Gql = qWord ? GQWl + (bh * LW + q0) * DHH
                            : GQEl + (bh * LE + (q0 - LW)) * DHH;

    // stage Q (once): 128 rows x 8 units of 16B = 1024 units per region
#pragma unroll
    for (int u = tid; u < 1024; u += 256) {
        int row = u >> 3, c = u & 7;
        cpa16(swz(smb + SM_QH, row, c), Qhg + (size_t)row * DHH + c * 8);
        cpa16(swz(smb + SM_QL, row, c), Qlg + (size_t)row * DHH + c * 8);
    }
    CP_COMMIT();

    // ldmatrix lane params
    const int aRow  = wid * 16 + (lane & 15);
    const int aC    = lane >> 4;
    const int bRow0 = (lane & 7) + ((lane >> 4) & 1) * 8;
    const int bC    = (lane >> 3) & 1;

    float o[8][4];
#pragma unroll
    for (int t = 0; t < 8; t++)
#pragma unroll
        for (int j = 0; j < 4; j++) o[t][j] = 0.0f;
    float m0 = -1e30f, m1 = -1e30f, ls0 = 0.0f, ls1 = 0.0f;

    const int r0  = wid * 16 + (lane >> 2);     // q row (and r0+8)
    const int prx = r0 & 7;
    const int pb  = 4 * (lane & 3);             // byte offset within 16B unit

    for (int kt = 0; kt < 10; kt++) {
        const int  k0    = kt * 64;
        const bool kWord = (k0 < LW);
        const bool cross = (kWord != qWord);

        __syncthreads();     // prev iter fully consumed P/V/R2

        // ---- stage this iteration ----
        {
            if (cross) {
                const bf16* gkh = qWord ? GKEh + (bh * LE + (k0 - LW)) * DHH
                                        : GKWh + (bh * LW + k0) * DHH;
                const bf16* gkl = qWord ? GKEl + (bh * LE + (k0 - LW)) * DHH
                                        : GKWl + (bh * LW + k0) * DHH;
#pragma unroll
                for (int u = tid; u < 1024; u += 256) {
                    int rr = u >> 3, cc = u & 7;
                    cpa16(swz(smb + SM_R1,  rr, cc), Gqh + (size_t)rr * DHH + cc * 8);
                    cpa16(swz(smb + SM_R1L, rr, cc), Gql + (size_t)rr * DHH + cc * 8);
                }
#pragma unroll
                for (int u = tid; u < 512; u += 256) {
                    int rr = u >> 3, cc = u & 7;
                    cpa16(swz(smb + SM_R2,  rr, cc), gkh + (size_t)rr * DHH + cc * 8);
                    cpa16(swz(smb + SM_R2L, rr, cc), gkl + (size_t)rr * DHH + cc * 8);
                }
            } else {
                const bf16* kh = Kh + (bh * LL + k0) * DHH;
                const bf16* kl = Kl + (bh * LL + k0) * DHH;
#pragma unroll
                for (int u = tid; u < 512; u += 256) {
                    int rr = u >> 3, cc = u & 7;
                    cpa16(swz(smb + SM_R2,  rr, cc), kh + (size_t)rr * DHH + cc * 8);
                    cpa16(swz(smb + SM_R2L, rr, cc), kl + (size_t)rr * DHH + cc * 8);
                }
            }
            // V^T tile: rows = dh (64), cols = kv (64)
            const bf16* vhB = Vth + bh * DHH * LL + k0;
            const bf16* vlB = Vtl + bh * DHH * LL + k0;
#pragma unroll
            for (int u = tid; u < 512; u += 256) {
                int rr = u >> 3, cc = u & 7;
                cpa16(swz(smb + SM_VH, rr, cc), vhB + (size_t)rr * LL + cc * 8);
                cpa16(swz(smb + SM_VL, rr, cc), vlB + (size_t)rr * LL + cc * 8);
            }
            if (tid < 16)
                cpa16(smb + SM_MS + tid * 16, mask + (size_t)b * LL + k0 + tid * 4);
            CP_COMMIT();
            CP_WAIT(0);
            __syncthreads();
        }

        float acc[8][4];
        if (cross) {
            // gate GEMM -> sigmoid transform -> becomes accumulator init
#pragma unroll
            for (int t = 0; t < 8; t++)
#pragma unroll
                for (int j = 0; j < 4; j++) acc[t][j] = 0.0f;
            gemm3(acc, smb + SM_R1, smb + SM_R1L, smb + SM_R2, smb + SM_R2L,
                  aRow, bRow0, aC, bC);
#pragma unroll
            for (int t = 0; t < 8; t++)
#pragma unroll
                for (int j = 0; j < 4; j++)
                    acc[t][j] = -10.0f / (1.0f + __expf(-acc[t][j]));
            __syncthreads();   // done reading Gk from R2
            {
                const bf16* kh = Kh + (bh * LL + k0) * DHH;
                const bf16* kl = Kl + (bh * LL + k0) * DHH;
#pragma unroll
                for (int u = tid; u < 512; u += 256) {
                    int rr = u >> 3, cc = u & 7;
                    cpa16(swz(smb + SM_R2,  rr, cc), kh + (size_t)rr * DHH + cc * 8);
                    cpa16(swz(smb + SM_R2L, rr, cc), kl + (size_t)rr * DHH + cc * 8);
                }
                CP_COMMIT();
                CP_WAIT(0);
                __syncthreads();
            }
        } else {
#pragma unroll
            for (int t = 0; t < 8; t++)
#pragma unroll
                for (int j = 0; j < 4; j++) acc[t][j] = -5.0f;
        }

        // S GEMM: Q * K^T accumulated onto gate
        gemm3(acc, smb + SM_QH, smb + SM_QL, smb + SM_R2, smb + SM_R2L,
              aRow, bRow0, aC, bC);

        // ---- online softmax ----
        float rmax0 = -1e30f, rmax1 = -1e30f;
#pragma unroll
        for (int t = 0; t < 8; t++) {
            int colb = t * 8 + 2 * (lane & 3);
            float mk0 = *(const float*)(smc + SM_MS + (colb) * 4);
            float mk1 = *(const float*)(smc + SM_MS + (colb + 1) * 4);
            acc[t][0] = acc[t][0] * 0.125f + mk0;
            acc[t][1] = acc[t][1] * 0.125f + mk1;
            acc[t][2] = acc[t][2] * 0.125f + mk0;
            acc[t][3] = acc[t][3] * 0.125f + mk1;
            rmax0 = fmaxf(rmax0, fmaxf(acc[t][0], acc[t][1]));
            rmax1 = fmaxf(rmax1, fmaxf(acc[t][2], acc[t][3]));
        }
#pragma unroll
        for (int off = 1; off <= 2; off <<= 1) {
            rmax0 = fmaxf(rmax0, __shfl_xor_sync(0xffffffffu, rmax0, off));
            rmax1 = fmaxf(rmax1, __shfl_xor_sync(0xffffffffu, rmax1, off));
        }
        float mn0 = fmaxf(m0, rmax0), mn1 = fmaxf(m1, rmax1);
        float corr0 = __expf(m0 - mn0), corr1 = __expf(m1 - mn1);
        m0 = mn0; m1 = mn1;
        float sum0 = 0.0f, sum1 = 0.0f;
#pragma unroll
        for (int t = 0; t < 8; t++) {
            acc[t][0] = __expf(acc[t][0] - mn0);
            acc[t][1] = __expf(acc[t][1] - mn0);
            acc[t][2] = __expf(acc[t][2] - mn1);
            acc[t][3] = __expf(acc[t][3] - mn1);
            sum0 += acc[t][0] + acc[t][1];
            sum1 += acc[t][2] + acc[t][3];
        }
#pragma unroll
        for (int off = 1; off <= 2; off <<= 1) {
            sum0 += __shfl_xor_sync(0xffffffffu, sum0, off);
            sum1 += __shfl_xor_sync(0xffffffffu, sum1, off);
        }
        ls0 = ls0 * corr0 + sum0;
        ls1 = ls1 * corr1 + sum1;
#pragma unroll
        for (int t = 0; t < 8; t++) {
            o[t][0] *= corr0; o[t][1] *= corr0;
            o[t][2] *= corr1; o[t][3] *= corr1;
        }

        // ---- store P (hi/lo bf16) into R1 ----
#pragma unroll
        for (int t = 0; t < 8; t++) {
            unsigned short h00,l00,h01,l01,h10,l10,h11,l11;
            bsplit(acc[t][0], h00, l00); bsplit(acc[t][1], h01, l01);
            bsplit(acc[t][2], h10, l10); bsplit(acc[t][3], h11, l11);
            uint32_t ofs = (uint32_t)(r0 * 128 + ((t ^ prx) << 4) + pb);
            *(uint32_t*)(smc + SM_R1  + ofs) = (uint32_t)h00 | ((uint32_t)h01 << 16);
            *(uint32_t*)(smc + SM_R1L + ofs) = (uint32_t)l00 | ((uint32_t)l01 << 16);
            *(uint32_t*)(smc + SM_R1  + ofs + 1024) = (uint32_t)h10 | ((uint32_t)h11 << 16);
            *(uint32_t*)(smc + SM_R1L + ofs + 1024) = (uint32_t)l10 | ((uint32_t)l11 << 16);
        }
        __syncthreads();

        // ---- PV GEMM: P * V^T ----
        gemm3(o, smb + SM_R1, smb + SM_R1L, smb + SM_VH, smb + SM_VL,
              aRow, bRow0, aC, bC);
    }

    // ---- epilogue ----
    float inv0 = 1.0f / ls0, inv1 = 1.0f / ls1;
    int q  = q0 + r0;
    size_t off0, off1;
    if (q < LW) {
        off0 = ((size_t)b * LW + q) * DD + h * DHH;
        off1 = ((size_t)b * LW + q + 8) * DD + h * DHH;
    } else {
        off0 = (size_t)BB * LW * DD + ((size_t)b * LE + (q - LW)) * DD + h * DHH;
        off1 = off0 + 8 * DD;
    }
#pragma unroll
    for (int t = 0; t < 8; t++) {
        int dh = t * 8 + 2 * (lane & 3);
        float2 r0v = {o[t][0] * inv0, o[t][1] * inv0};
        float2 r1v = {o[t][2] * inv1, o[t][3] * inv1};
        *(float2*)(out + off0 + dh) = r0v;
        *(float2*)(out + off1 + dh) = r1v;
    }
}

// ---------------------------------------------------------------------------
// Launch
// ---------------------------------------------------------------------------
extern "C" void kernel_launch(void* const* d_in, const int* in_sizes, int n_in,
                              void* d_out, int out_size)
{
    const float* word   = (const float*)d_in[0];
    const float* entity = (const float*)d_in[1];
    const float* mask   = (const float*)d_in[2];
    int base = (in_sizes[3] == 1) ? 4 : 3;
    const float* qw     = (const float*)d_in[base + 0];
    const float* qb     = (const float*)d_in[base + 1];
    const float* kw     = (const float*)d_in[base + 2];
    const float* kb     = (const float*)d_in[base + 3];
    const float* vw     = (const float*)d_in[base + 4];
    const float* vb     = (const float*)d_in[base + 5];
    const float* w2e_qw = (const float*)d_in[base + 6];
    const float* w2e_qb = (const float*)d_in[base + 7];
    const float* w2e_kw = (const float*)d_in[base + 8];
    const float* w2e_kb = (const float*)d_in[base + 9];
    const float* e2w_qw = (const float*)d_in[base + 10];
    const float* e2w_qb = (const float*)d_in[base + 11];
    const float* e2w_kw = (const float*)d_in[base + 12];
    const float* e2w_kb = (const float*)d_in[base + 13];

    bf16 *pQh,*pQl,*pKh,*pKl,*pVth,*pVtl;
    bf16 *pGQWh,*pGQWl,*pGKWh,*pGKWl,*pGQEh,*pGQEl,*pGKEh,*pGKEl;
    bf16 *pXhi,*pXlo,*pWhi,*pWlo;
    cudaGetSymbolAddress((void**)&pQh,  g_Qh);   cudaGetSymbolAddress((void**)&pQl,  g_Ql);
    cudaGetSymbolAddress((void**)&pKh,  g_Kh);   cudaGetSymbolAddress((void**)&pKl,  g_Kl);
    cudaGetSymbolAddress((void**)&pVth, g_Vth);  cudaGetSymbolAddress((void**)&pVtl, g_Vtl);
    cudaGetSymbolAddress((void**)&pGQWh,g_GQWh); cudaGetSymbolAddress((void**)&pGQWl,g_GQWl);
    cudaGetSymbolAddress((void**)&pGKWh,g_GKWh); cudaGetSymbolAddress((void**)&pGKWl,g_GKWl);
    cudaGetSymbolAddress((void**)&pGQEh,g_GQEh); cudaGetSymbolAddress((void**)&pGQEl,g_GQEl);
    cudaGetSymbolAddress((void**)&pGKEh,g_GKEh); cudaGetSymbolAddress((void**)&pGKEl,g_GKEl);
    cudaGetSymbolAddress((void**)&pXhi, g_Xhi);  cudaGetSymbolAddress((void**)&pXlo, g_Xlo);
    cudaGetSymbolAddress((void**)&pWhi, g_Whi);  cudaGetSymbolAddress((void**)&pWlo, g_Wlo);

    // ---- split pass ----
    split_act<<<BB * LL, 256>>>(word, entity, pXhi, pXlo);
    split_wt<<<dim3(32, 32, 7), dim3(32, 8)>>>(
        qw, kw, vw, w2e_qw, w2e_kw, e2w_qw, e2w_kw, pWhi, pWlo);

    // ---- HMMA projections ----
    const size_t psmem = 2 * PBUF;
    cudaFuncSetAttribute(proj_mma,
                         cudaFuncAttributeMaxDynamicSharedMemorySize, (int)psmem);
    const size_t WSZ = (size_t)DD * DD;
    proj_mma<<<dim3(80, 8), 256, psmem>>>(pXhi, pXlo, pWhi + 0*WSZ, pWlo + 0*WSZ, qb,     pQh,  pQl,  LL, 0,  0);
    proj_mma<<<dim3(80, 8), 256, psmem>>>(pXhi, pXlo, pWhi + 1*WSZ, pWlo + 1*WSZ, kb,     pKh,  pKl,  LL, 0,  0);
    proj_mma<<<dim3(80, 8), 256, psmem>>>(pXhi, pXlo, pWhi + 2*WSZ, pWlo + 2*WSZ, vb,     pVth, pVtl, LL, 0,  1);
    proj_mma<<<dim3(64, 8), 256, psmem>>>(pXhi, pXlo, pWhi + 3*WSZ, pWlo + 3*WSZ, w2e_qb, pGQWh,pGQWl,LW, 0,  0);
    proj_mma<<<dim3(16, 8), 256, psmem>>>(pXhi, pXlo, pWhi + 4*WSZ, pWlo + 4*WSZ, w2e_kb, pGKEh,pGKEl,LE, LW, 0);
    proj_mma<<<dim3(16, 8), 256, psmem>>>(pXhi, pXlo, pWhi + 5*WSZ, pWlo + 5*WSZ, e2w_qb, pGQEh,pGQEl,LE, LW, 0);
    proj_mma<<<dim3(64, 8), 256, psmem>>>(pXhi, pXlo, pWhi + 6*WSZ, pWlo + 6*WSZ, e2w_kb, pGKWh,pGKWl,LW, 0,  0);

    // ---- HMMA attention ----
    cudaFuncSetAttribute(attn_mma,
                         cudaFuncAttributeMaxDynamicSharedMemorySize, (int)ATT_SMEM);
    attn_mma<<<dim3(5, HH, BB), 256, ATT_SMEM>>>(
        pQh, pQl, pKh, pKl, pVth, pVtl,
        pGQWh, pGQWl, pGKWh, pGKWl, pGQEh, pGQEl, pGKEh, pGKEl,
        mask, (float*)d_out);
}